// round 14
// baseline (speedup 1.0000x reference)
#include <cuda_runtime.h>
#include <cuda_bf16.h>
#include <cstdint>
#include <math.h>

#define BB 4
#define TT 2048
#define CC 1024
#define HH 16
#define HD 64
#define BH (BB*HH)   /* 64 */
#define MM (BB*TT)   /* 8192 */

// ------------------------- scratch (static device globals; no allocs) ---------
__device__ __nv_bfloat16 g_xb[(size_t)MM*CC];          // x in bf16
__device__ __nv_bfloat16 g_WT[4][(size_t)CC*CC];       // Wq,Wk,Wv,Wo transposed [n][k] bf16
__device__ __nv_bfloat16 g_bias[4][CC];                // bq,bk,bv,bo bf16
__device__ __nv_bfloat16 g_q[(size_t)BH*TT*HD];        // [bh][t][d] post-rope bf16
__device__ __nv_bfloat16 g_k[(size_t)BH*TT*HD];
__device__ __nv_bfloat16 g_v[(size_t)BH*TT*HD];
__device__ __nv_bfloat16 g_S[(size_t)BH*TT*TT];        // bf16 scaled logits (lower-tri tiles)
__device__ __nv_bfloat16 g_y[(size_t)MM*CC];           // attention output bf16 [b*T+t][h*64+d]
__device__ float         g_cos[TT*(HD/2)];
__device__ float         g_sin[TT*(HD/2)];

// ------------------------- packed f32x2 primitives (sm_100a) ------------------
__device__ __forceinline__ uint64_t f32x2pk(float a, float b) {
    uint64_t r; asm("mov.b64 %0, {%1,%2};" : "=l"(r) : "f"(a), "f"(b)); return r;
}
__device__ __forceinline__ void f32x2upk(uint64_t v, float& a, float& b) {
    asm("mov.b64 {%0,%1}, %2;" : "=f"(a), "=f"(b) : "l"(v));
}
__device__ __forceinline__ uint64_t fma2(uint64_t a, uint64_t b, uint64_t c) {
    uint64_t d; asm("fma.rn.f32x2 %0,%1,%2,%3;" : "=l"(d) : "l"(a), "l"(b), "l"(c)); return d;
}
__device__ __forceinline__ uint64_t mul2(uint64_t a, uint64_t b) {
    uint64_t d; asm("mul.rn.f32x2 %0,%1,%2;" : "=l"(d) : "l"(a), "l"(b)); return d;
}
__device__ __forceinline__ uint64_t add2(uint64_t a, uint64_t b) {
    uint64_t d; asm("add.rn.f32x2 %0,%1,%2;" : "=l"(d) : "l"(a), "l"(b)); return d;
}

// Pairwise accurate exp: per-lane op sequence IDENTICAL to scalar exp_rn (R5-R13).
__device__ __forceinline__ void exp_rn2(float x0, float x1, float& o0, float& o1) {
    x0 = fmaxf(x0, -87.0f); x1 = fmaxf(x1, -87.0f);
    uint64_t X = f32x2pk(x0, x1);
    uint64_t T = fma2(X, f32x2pk(1.44269504088896341f, 1.44269504088896341f),
                         f32x2pk(0.5f, 0.5f));
    float t0, t1; f32x2upk(T, t0, t1);
    float mf0 = floorf(t0), mf1 = floorf(t1);
    uint64_t MF = f32x2pk(mf0, mf1);
    uint64_t R = fma2(MF, f32x2pk(-0.693359375f, -0.693359375f), X);
    R = fma2(MF, f32x2pk(2.12194440e-4f, 2.12194440e-4f), R);
    uint64_t P = f32x2pk(1.9875691500e-4f, 1.9875691500e-4f);
    P = fma2(P, R, f32x2pk(1.3981999507e-3f, 1.3981999507e-3f));
    P = fma2(P, R, f32x2pk(8.3334519073e-3f, 8.3334519073e-3f));
    P = fma2(P, R, f32x2pk(4.1665795894e-2f, 4.1665795894e-2f));
    P = fma2(P, R, f32x2pk(1.6666665459e-1f, 1.6666665459e-1f));
    P = fma2(P, R, f32x2pk(5.0000001201e-1f, 5.0000001201e-1f));
    uint64_t Y = fma2(P, mul2(R, R), R);
    Y = add2(Y, f32x2pk(1.0f, 1.0f));
    int mi0 = (int)mf0, mi1 = (int)mf1;
    uint64_t SC = f32x2pk(__int_as_float((mi0 + 127) << 23),
                          __int_as_float((mi1 + 127) << 23));
    Y = mul2(Y, SC);
    f32x2upk(Y, o0, o1);
}

// ------------------------- mma.sync m16n8k16 bf16 -----------------------------
__device__ __forceinline__ void mma_bf16(float c[4], const uint32_t a[4], const uint32_t b[2]) {
    asm volatile(
        "mma.sync.aligned.m16n8k16.row.col.f32.bf16.bf16.f32 "
        "{%0,%1,%2,%3}, {%4,%5,%6,%7}, {%8,%9}, {%0,%1,%2,%3};\n"
        : "+f"(c[0]), "+f"(c[1]), "+f"(c[2]), "+f"(c[3])
        : "r"(a[0]), "r"(a[1]), "r"(a[2]), "r"(a[3]), "r"(b[0]), "r"(b[1]));
}

__device__ __forceinline__ void ldsm_x4(uint32_t r[4], uint32_t addr) {
    asm volatile("ldmatrix.sync.aligned.m8n8.x4.shared.b16 {%0,%1,%2,%3}, [%4];"
                 : "=r"(r[0]), "=r"(r[1]), "=r"(r[2]), "=r"(r[3]) : "r"(addr));
}
__device__ __forceinline__ void ldsm_x4t(uint32_t r[4], uint32_t addr) {
    asm volatile("ldmatrix.sync.aligned.m8n8.x4.trans.shared.b16 {%0,%1,%2,%3}, [%4];"
                 : "=r"(r[0]), "=r"(r[1]), "=r"(r[2]), "=r"(r[3]) : "r"(addr));
}

// ------------------------- prep kernels ---------------------------------------
__global__ void k_conv_x(const float* __restrict__ x) {
    size_t i = ((size_t)blockIdx.x * 256 + threadIdx.x) * 4;
    float4 v = *(const float4*)(x + i);
    __nv_bfloat162 a, b;
    a.x = __float2bfloat16(v.x); a.y = __float2bfloat16(v.y);
    b.x = __float2bfloat16(v.z); b.y = __float2bfloat16(v.w);
    *(__nv_bfloat162*)(g_xb + i)     = a;
    *(__nv_bfloat162*)(g_xb + i + 2) = b;
}

__global__ void k_prepW(const float* __restrict__ Wq, const float* __restrict__ Wk,
                        const float* __restrict__ Wv, const float* __restrict__ Wo,
                        const float* __restrict__ bq, const float* __restrict__ bk,
                        const float* __restrict__ bv, const float* __restrict__ bo) {
    const float* W = (blockIdx.z == 0) ? Wq : (blockIdx.z == 1) ? Wk : (blockIdx.z == 2) ? Wv : Wo;
    __shared__ float tile[32][33];
    int n0 = blockIdx.x * 32, k0 = blockIdx.y * 32;
    for (int jj = threadIdx.y; jj < 32; jj += 8)
        tile[jj][threadIdx.x] = W[(size_t)(k0 + jj) * CC + n0 + threadIdx.x];
    if (blockIdx.y == 0 && threadIdx.y == 0) {
        const float* p = (blockIdx.z == 0) ? bq : (blockIdx.z == 1) ? bk
                       : (blockIdx.z == 2) ? bv : bo;
        g_bias[blockIdx.z][n0 + threadIdx.x] = __float2bfloat16(p[n0 + threadIdx.x]);
    }
    __syncthreads();
    for (int jj = threadIdx.y; jj < 32; jj += 8)
        g_WT[blockIdx.z][(size_t)(n0 + jj) * CC + k0 + threadIdx.x] =
            __float2bfloat16(tile[threadIdx.x][jj]);
}

__global__ void k_rope() {
    int t = blockIdx.x, j = threadIdx.x;                 // j in 0..31
    double e = (double)(2 * j) / 64.0;
    float p32 = (float)pow(10000.0, e);
    float inv = __fdiv_rn(1.0f, p32);
    float ang = __fmul_rn((float)t, inv);
    g_cos[t * (HD/2) + j] = (float)cos((double)ang);
    g_sin[t * (HD/2) + j] = (float)sin((double)ang);
}

// ------------------------- GEMM: x@W (+bias, rope) / y@Wo --------------------
#define GSTAGE 36864
#define GSMEM  (2*GSTAGE)

__global__ __launch_bounds__(256) void k_gemm(int mode_base, float* __restrict__ outF)
{
    extern __shared__ unsigned char gsm[];
    const int mode = mode_base + blockIdx.z;
    const __nv_bfloat16* __restrict__ A  = (mode < 3) ? g_xb : g_y;
    const __nv_bfloat16* __restrict__ Bt = g_WT[mode];
    const __nv_bfloat16* __restrict__ bs = g_bias[mode];
    const int m0 = blockIdx.y * 128;
    const int n0 = blockIdx.x * 128;

    const int tid = threadIdx.x;
    const int wid = tid >> 5, lane = tid & 31;
    const int g = lane >> 2, t4 = lane & 3;
    const int wm = wid & 3, wn = wid >> 2;
    const int lb = lane >> 3, lr = lane & 7;

    float acc[16][4];
    #pragma unroll
    for (int i = 0; i < 16; i++) { acc[i][0] = acc[i][1] = acc[i][2] = acc[i][3] = 0.f; }

    {
        __nv_bfloat16* sA = (__nv_bfloat16*)gsm;
        __nv_bfloat16* sB = (__nv_bfloat16*)(gsm + GSTAGE / 2);
        #pragma unroll
        for (int rep = 0; rep < 4; rep++) {
            int i = tid + rep * 256;
            int row = i >> 3, cg = i & 7;
            uint32_t da = (uint32_t)__cvta_generic_to_shared(sA + row * 72 + cg * 8);
            uint32_t db = (uint32_t)__cvta_generic_to_shared(sB + row * 72 + cg * 8);
            asm volatile("cp.async.cg.shared.global [%0], [%1], 16;\n"
                         :: "r"(da), "l"(A  + (size_t)(m0 + row) * CC + cg * 8));
            asm volatile("cp.async.cg.shared.global [%0], [%1], 16;\n"
                         :: "r"(db), "l"(Bt + (size_t)(n0 + row) * CC + cg * 8));
        }
        asm volatile("cp.async.commit_group;\n");
    }

    for (int it = 0; it < 16; it++) {
        asm volatile("cp.async.wait_group 0;\n");
        __syncthreads();
        if (it + 1 < 16) {
            int k0 = (it + 1) * 64;
            unsigned char* stg = gsm + ((it + 1) & 1) * GSTAGE;
            __nv_bfloat16* sA = (__nv_bfloat16*)stg;
            __nv_bfloat16* sB = (__nv_bfloat16*)(stg + GSTAGE / 2);
            #pragma unroll
            for (int rep = 0; rep < 4; rep++) {
                int i = tid + rep * 256;
                int row = i >> 3, cg = i & 7;
                uint32_t da = (uint32_t)__cvta_generic_to_shared(sA + row * 72 + cg * 8);
                uint32_t db = (uint32_t)__cvta_generic_to_shared(sB + row * 72 + cg * 8);
                asm volatile("cp.async.cg.shared.global [%0], [%1], 16;\n"
                             :: "r"(da), "l"(A  + (size_t)(m0 + row) * CC + k0 + cg * 8));
                asm volatile("cp.async.cg.shared.global [%0], [%1], 16;\n"
                             :: "r"(db), "l"(Bt + (size_t)(n0 + row) * CC + k0 + cg * 8));
            }
            asm volatile("cp.async.commit_group;\n");
        }
        const __nv_bfloat16* sA = (const __nv_bfloat16*)(gsm + (it & 1) * GSTAGE);
        const __nv_bfloat16* sB = (const __nv_bfloat16*)(gsm + (it & 1) * GSTAGE + GSTAGE / 2);
        #pragma unroll
        for (int ks = 0; ks < 64; ks += 16) {
            uint32_t af[2][4];
            #pragma unroll
            for (int mt = 0; mt < 2; mt++) {
                int row = wm * 32 + mt * 16 + (lb & 1) * 8 + lr;
                int col = ks + (lb >> 1) * 8;
                ldsm_x4(af[mt], (uint32_t)__cvta_generic_to_shared(sA + row * 72 + col));
            }
            uint32_t bfr[8][2];
            #pragma unroll
            for (int p = 0; p < 4; p++) {
                int row = wn * 64 + (2 * p + (lb >> 1)) * 8 + lr;
                int col = ks + (lb & 1) * 8;
                uint32_t q[4];
                ldsm_x4(q, (uint32_t)__cvta_generic_to_shared(sB + row * 72 + col));
                bfr[2 * p][0] = q[0]; bfr[2 * p][1] = q[1];
                bfr[2 * p + 1][0] = q[2]; bfr[2 * p + 1][1] = q[3];
            }
            #pragma unroll
            for (int mt = 0; mt < 2; mt++)
                #pragma unroll
                for (int nt = 0; nt < 8; nt++)
                    mma_bf16(acc[mt * 8 + nt], af[mt], bfr[nt]);
        }
    }

    #pragma unroll
    for (int mt = 0; mt < 2; mt++) {
        #pragma unroll
        for (int nt = 0; nt < 8; nt++) {
            float* c = acc[mt * 8 + nt];
            int col = n0 + wn * 64 + nt * 8 + 2 * t4;
            int r0  = m0 + wm * 32 + mt * 16 + g;
            #pragma unroll
            for (int hf = 0; hf < 2; hf++) {
                int row = r0 + hf * 8;
                __nv_bfloat16 eb = __hadd(__float2bfloat16(c[hf * 2 + 0]), bs[col]);
                __nv_bfloat16 ob = __hadd(__float2bfloat16(c[hf * 2 + 1]), bs[col + 1]);
                if (mode == 3) {
                    outF[(size_t)row * CC + col]     = __bfloat162float(eb);
                    outF[(size_t)row * CC + col + 1] = __bfloat162float(ob);
                } else {
                    int b = row >> 11, t = row & (TT - 1);
                    int h = col >> 6,  d = col & 63;
                    size_t oidx = ((size_t)(b * HH + h) * TT + t) * HD + d;
                    __nv_bfloat162 pr;
                    if (mode <= 1) {
                        int j = d >> 1;
                        float cth = g_cos[t * (HD/2) + j], sth = g_sin[t * (HD/2) + j];
                        float ef = __bfloat162float(eb), of = __bfloat162float(ob);
                        float re = __fsub_rn(__fmul_rn(ef, cth), __fmul_rn(of, sth));
                        float ro = __fadd_rn(__fmul_rn(ef, sth), __fmul_rn(of, cth));
                        pr.x = __float2bfloat16(re);
                        pr.y = __float2bfloat16(ro);
                    } else {
                        pr.x = eb; pr.y = ob;
                    }
                    __nv_bfloat16* outp = (mode == 0) ? g_q : (mode == 1) ? g_k : g_v;
                    *(__nv_bfloat162*)(outp + oidx) = pr;
                }
            }
        }
    }
}

// --------- fused attention, q-tile 128, 32x32 warp tiles ----------------------
// dynamic smem overlay: phase A {sQ 18432 | sK[2] 18432}, phase B {sP[2] 36864},
// V[2] 18432 at offset 36864 (disjoint). total 55296 B.
#define ATT_SMEM 55296

__global__ __launch_bounds__(256) void k_att()
{
    extern __shared__ __align__(16) unsigned char buf[];
    __shared__ float sMax[2][128];
    __shared__ float sMfin[128];
    __shared__ float sLfin[128];

    const int qt = 15 - blockIdx.x;                      // heavy tiles first
    const int bh = blockIdx.y;
    const int q0 = qt * 128;
    const int nkt = 2 * qt + 2;                          // 64-key tiles
    const __nv_bfloat16* __restrict__ Q = g_q + (size_t)bh * TT * HD;
    const __nv_bfloat16* __restrict__ K = g_k + (size_t)bh * TT * HD;
    const __nv_bfloat16* __restrict__ V = g_v + (size_t)bh * TT * HD;

    const int tid = threadIdx.x;
    const int wid = tid >> 5, lane = tid & 31;
    const int g = lane >> 2, t4 = lane & 3;
    const int wm = wid & 3, wn = wid >> 2;               // 4x2 warp grid, 32x32 tiles
    const int lb = lane >> 3, lr = lane & 7;

    // ===================== phase A: S = bf16(QK^T)*0.125, max, l ==============
    {
        __nv_bfloat16* sQ = (__nv_bfloat16*)buf;                     // 128*72*2
        #pragma unroll
        for (int rep = 0; rep < 4; rep++) {
            int i = tid + rep * 256;
            int row = i >> 3, cg = i & 7;
            *(uint4*)&sQ[row * 72 + cg * 8] = *(const uint4*)(Q + (size_t)(q0 + row) * HD + cg * 8);
        }
        // prestage K tile 0
        #pragma unroll
        for (int rep = 0; rep < 2; rep++) {
            int i = tid + rep * 256;
            int row = i >> 3, cg = i & 7;
            uint32_t dst = (uint32_t)__cvta_generic_to_shared(buf + 18432 + (row * 72 + cg * 8) * 2);
            asm volatile("cp.async.cg.shared.global [%0], [%1], 16;\n"
                         :: "r"(dst), "l"(K + (size_t)row * HD + cg * 8));
        }
        asm volatile("cp.async.commit_group;\n");

        float rmax[2][2];
        rmax[0][0] = rmax[0][1] = rmax[1][0] = rmax[1][1] = -INFINITY;

        for (int kt = 0; kt < nkt; kt++) {
            asm volatile("cp.async.wait_group 0;\n");
            __syncthreads();
            if (kt + 1 < nkt) {
                unsigned char* dstb = buf + 18432 + ((kt + 1) & 1) * 9216;
                #pragma unroll
                for (int rep = 0; rep < 2; rep++) {
                    int i = tid + rep * 256;
                    int row = i >> 3, cg = i & 7;
                    uint32_t dst = (uint32_t)__cvta_generic_to_shared(dstb + (row * 72 + cg * 8) * 2);
                    asm volatile("cp.async.cg.shared.global [%0], [%1], 16;\n"
                                 :: "r"(dst), "l"(K + (size_t)((kt + 1) * 64 + row) * HD + cg * 8));
                }
                asm volatile("cp.async.commit_group;\n");
            }
            const __nv_bfloat16* sKb = (const __nv_bfloat16*)(buf + 18432 + (kt & 1) * 9216);
            float acc[2][4][4] = {};
            #pragma unroll
            for (int ks = 0; ks < 64; ks += 16) {
                uint32_t af[2][4];
                #pragma unroll
                for (int mt = 0; mt < 2; mt++) {
                    int row = wm * 32 + mt * 16 + (lb & 1) * 8 + lr;
                    int col = ks + (lb >> 1) * 8;
                    ldsm_x4(af[mt], (uint32_t)__cvta_generic_to_shared(sQ + row * 72 + col));
                }
                uint32_t kf[4][2];
                #pragma unroll
                for (int p = 0; p < 2; p++) {
                    int row = wn * 32 + (2 * p + (lb >> 1)) * 8 + lr;
                    int col = ks + (lb & 1) * 8;
                    uint32_t q4[4];
                    ldsm_x4(q4, (uint32_t)__cvta_generic_to_shared(sKb + row * 72 + col));
                    kf[2 * p][0] = q4[0]; kf[2 * p][1] = q4[1];
                    kf[2 * p + 1][0] = q4[2]; kf[2 * p + 1][1] = q4[3];
                }
                #pragma unroll
                for (int mt = 0; mt < 2; mt++)
                    #pragma unroll
                    for (int nt = 0; nt < 4; nt++)
                        mma_bf16(acc[mt][nt], af[mt], kf[nt]);
            }
            #pragma unroll
            for (int mt = 0; mt < 2; mt++) {
                const int qg0 = q0 + wm * 32 + mt * 16 + g;
                const int qg1 = qg0 + 8;
                #pragma unroll
                for (int nt = 0; nt < 4; nt++) {
                    int kc = kt * 64 + wn * 32 + nt * 8 + 2 * t4;
                    {
                        float s0 = __fmul_rn(__bfloat162float(__float2bfloat16(acc[mt][nt][0])), 0.125f);
                        float s1 = __fmul_rn(__bfloat162float(__float2bfloat16(acc[mt][nt][1])), 0.125f);
                        if (kc     <= qg0) rmax[mt][0] = fmaxf(rmax[mt][0], s0);
                        if (kc + 1 <= qg0) rmax[mt][0] = fmaxf(rmax[mt][0], s1);
                        __nv_bfloat162 pr; pr.x = __float2bfloat16(s0); pr.y = __float2bfloat16(s1);
                        *(__nv_bfloat162*)(g_S + (size_t)(bh * TT + qg0) * TT + kc) = pr;
                    }
                    {
                        float s0 = __fmul_rn(__bfloat162float(__float2bfloat16(acc[mt][nt][2])), 0.125f);
                        float s1 = __fmul_rn(__bfloat162float(__float2bfloat16(acc[mt][nt][3])), 0.125f);
                        if (kc     <= qg1) rmax[mt][1] = fmaxf(rmax[mt][1], s0);
                        if (kc + 1 <= qg1) rmax[mt][1] = fmaxf(rmax[mt][1], s1);
                        __nv_bfloat162 pr; pr.x = __float2bfloat16(s0); pr.y = __float2bfloat16(s1);
                        *(__nv_bfloat162*)(g_S + (size_t)(bh * TT + qg1) * TT + kc) = pr;
                    }
                }
            }
        }
        #pragma unroll
        for (int mt = 0; mt < 2; mt++) {
            rmax[mt][0] = fmaxf(rmax[mt][0], __shfl_xor_sync(0xffffffffu, rmax[mt][0], 1));
            rmax[mt][0] = fmaxf(rmax[mt][0], __shfl_xor_sync(0xffffffffu, rmax[mt][0], 2));
            rmax[mt][1] = fmaxf(rmax[mt][1], __shfl_xor_sync(0xffffffffu, rmax[mt][1], 1));
            rmax[mt][1] = fmaxf(rmax[mt][1], __shfl_xor_sync(0xffffffffu, rmax[mt][1], 2));
            if (t4 == 0) {
                sMax[wn][wm * 32 + mt * 16 + g]     = rmax[mt][0];
                sMax[wn][wm * 32 + mt * 16 + g + 8] = rmax[mt][1];
            }
        }
        __syncthreads();
        if (tid < 128) sMfin[tid] = fmaxf(sMax[0][tid], sMax[1][tid]);
        __syncthreads();   // S writes + sMfin visible; all phase-A mma done

        // V tile 0 prestage (region disjoint from phase A buffers)
        #pragma unroll
        for (int rep = 0; rep < 2; rep++) {
            int i = tid + rep * 256;
            int row = i >> 3, cg = i & 7;
            uint32_t dst = (uint32_t)__cvta_generic_to_shared(buf + 36864 + (row * 72 + cg * 8) * 2);
            asm volatile("cp.async.cg.shared.global [%0], [%1], 16;\n"
                         :: "r"(dst), "l"(V + (size_t)row * HD + cg * 8));
        }
        asm volatile("cp.async.commit_group;\n");

        // l-pass: 2 rows per thread, per-row op order identical to R13
        {
            const int prow = tid >> 2;
            const int pcb  = (tid & 3) * 16;
            #pragma unroll
            for (int half = 0; half < 2; half++) {
                const int r = prow + half * 64;
                const int qgp = q0 + r;
                const float mrow = sMfin[r];
                const __nv_bfloat16* __restrict__ Srow = g_S + (size_t)(bh * TT + qgp) * TT;
                float lp = 0.f;
                uint4 c0 = *(const uint4*)(Srow + pcb);
                uint4 c1 = *(const uint4*)(Srow + pcb + 8);
                for (int kt = 0; kt < nkt; kt++) {
                    uint4 n0v, n1v;
                    if (kt + 1 < nkt) {
                        n0v = *(const uint4*)(Srow + (kt + 1) * 64 + pcb);
                        n1v = *(const uint4*)(Srow + (kt + 1) * 64 + pcb + 8);
                    }
                    __nv_bfloat16 hv[16];
                    *(uint4*)&hv[0] = c0;
                    *(uint4*)&hv[8] = c1;
                    #pragma unroll
                    for (int j = 0; j < 16; j += 2) {
                        int col = kt * 64 + pcb + j;
                        float e0, e1;
                        exp_rn2(__fsub_rn(__bfloat162float(hv[j]),     mrow),
                                __fsub_rn(__bfloat162float(hv[j + 1]), mrow), e0, e1);
                        if (col     <= qgp) lp = __fadd_rn(lp, e0);
                        if (col + 1 <= qgp) lp = __fadd_rn(lp, e1);
                    }
                    c0 = n0v; c1 = n1v;
                }
                lp = __fadd_rn(lp, __shfl_xor_sync(0xffffffffu, lp, 1));
                lp = __fadd_rn(lp, __shfl_xor_sync(0xffffffffu, lp, 2));
                if ((tid & 3) == 0) sLfin[r] = lp;
            }
        }
    }
    __syncthreads();   // sLfin ready; phase A smem (sQ/sK) dead from here

    // ===================== phase B: p = bf16(softmax), y = P@V^T ===============
    {
        const int prow = tid >> 2;
        const int pcb  = (tid & 3) * 16;

        float acc[2][4][4] = {};

        // prolog: prefetch S chunks(kt=0) for both rows (V tile 0 in flight)
        const __nv_bfloat16* SrowA = g_S + (size_t)(bh * TT + q0 + prow) * TT;
        const __nv_bfloat16* SrowB = g_S + (size_t)(bh * TT + q0 + prow + 64) * TT;
        uint4 sa0 = *(const uint4*)(SrowA + pcb);
        uint4 sa1 = *(const uint4*)(SrowA + pcb + 8);
        uint4 sb0 = *(const uint4*)(SrowB + pcb);
        uint4 sb1 = *(const uint4*)(SrowB + pcb + 8);

        for (int kt = 0; kt < nkt; kt++) {
            const int bsel = kt & 1;
            __nv_bfloat16* sPb = (__nv_bfloat16*)(buf + bsel * 18432);
            const __nv_bfloat16* sVb = (const __nv_bfloat16*)(buf + 36864 + bsel * 9216);
            // probabilities for both rows (reference rounding, ops per-row unchanged)
            {
                __nv_bfloat16 hva[16], hvb[16];
                *(uint4*)&hva[0] = sa0; *(uint4*)&hva[8] = sa1;
                *(uint4*)&hvb[0] = sb0; *(uint4*)&hvb[8] = sb1;
                const int qgA = q0 + prow, qgB = q0 + prow + 64;
                const float mA = sMfin[prow], lA = sLfin[prow];
                const float mB = sMfin[prow + 64], lB = sLfin[prow + 64];
                #pragma unroll
                for (int j = 0; j < 16; j += 2) {
                    int col = kt * 64 + pcb + j;
                    float e0, e1;
                    exp_rn2(__fsub_rn(__bfloat162float(hva[j]),     mA),
                            __fsub_rn(__bfloat162float(hva[j + 1]), mA), e0, e1);
                    __nv_bfloat162 pr;
                    pr.x = (col     <= qgA) ? __float2bfloat16(__fdiv_rn(e0, lA))
                                            : __float2bfloat16(0.f);
                    pr.y = (col + 1 <= qgA) ? __float2bfloat16(__fdiv_rn(e1, lA))
                                            : __float2bfloat16(0.f);
                    *(__nv_bfloat162*)&sPb[prow * 72 + pcb + j] = pr;
                    exp_rn2(__fsub_rn(__bfloat162float(hvb[j]),     mB),
                            __fsub_rn(__bfloat162float(hvb[j + 1]), mB), e0, e1);
                    pr.x = (col     <= qgB) ? __float2bfloat16(__fdiv_rn(e0, lB))
                                            : __float2bfloat16(0.f);
                    pr.y = (col + 1 <= qgB) ? __float2bfloat16(__fdiv_rn(e1, lB))
                                            : __float2bfloat16(0.f);
                    *(__nv_bfloat162*)&sPb[(prow + 64) * 72 + pcb + j] = pr;
                }
            }
            asm volatile("cp.async.wait_group 0;\n");
            __syncthreads();            // sP[bsel] + V(kt) visible; prev mma done
            if (kt + 1 < nkt) {
                unsigned char* dstb = buf + 36864 + ((kt + 1) & 1) * 9216;
                #pragma unroll
                for (int rep = 0; rep < 2; rep++) {
                    int i = tid + rep * 256;
                    int row = i >> 3, cg = i & 7;
                    uint32_t dst = (uint32_t)__cvta_generic_to_shared(dstb + (row * 72 + cg * 8) * 2);
                    asm volatile("cp.async.cg.shared.global [%0], [%1], 16;\n"
                                 :: "r"(dst), "l"(V + (size_t)((kt + 1) * 64 + row) * HD + cg * 8));
                }
                asm volatile("cp.async.commit_group;\n");
                sa0 = *(const uint4*)(SrowA + (kt + 1) * 64 + pcb);
                sa1 = *(const uint4*)(SrowA + (kt + 1) * 64 + pcb + 8);
                sb0 = *(const uint4*)(SrowB + (kt + 1) * 64 + pcb);
                sb1 = *(const uint4*)(SrowB + (kt + 1) * 64 + pcb + 8);
            }
            #pragma unroll
            for (int ks = 0; ks < 64; ks += 16) {
                uint32_t af[2][4];
                #pragma unroll
                for (int mt = 0; mt < 2; mt++) {
                    int row = wm * 32 + mt * 16 + (lb & 1) * 8 + lr;
                    int col = ks + (lb >> 1) * 8;
                    ldsm_x4(af[mt], (uint32_t)__cvta_generic_to_shared(sPb + row * 72 + col));
                }
                uint32_t vf[4][2];
                #pragma unroll
                for (int p = 0; p < 2; p++) {
                    int vrow = ks + (lane & 7) + ((lane >> 3) & 1) * 8;
                    int vcol = wn * 32 + p * 16 + (lane >> 4) * 8;
                    uint32_t q4[4];
                    ldsm_x4t(q4, (uint32_t)__cvta_generic_to_shared(sVb + vrow * 72 + vcol));
                    vf[2 * p][0] = q4[0]; vf[2 * p][1] = q4[1];
                    vf[2 * p + 1][0] = q4[2]; vf[2 * p + 1][1] = q4[3];
                }
                #pragma unroll
                for (int mt = 0; mt < 2; mt++)
                    #pragma unroll
                    for (int nt = 0; nt < 4; nt++)
                        mma_bf16(acc[mt][nt], af[mt], vf[nt]);
            }
        }

        const int b = bh >> 4, h = bh & 15;
        #pragma unroll
        for (int mt = 0; mt < 2; mt++)
            #pragma unroll
            for (int nt = 0; nt < 4; nt++) {
                int dcol = wn * 32 + nt * 8 + 2 * t4;
                #pragma unroll
                for (int hf = 0; hf < 2; hf++) {
                    int trow = q0 + wm * 32 + mt * 16 + g + hf * 8;
                    __nv_bfloat162 pr;
                    pr.x = __float2bfloat16(acc[mt][nt][hf * 2 + 0]);
                    pr.y = __float2bfloat16(acc[mt][nt][hf * 2 + 1]);
                    *(__nv_bfloat162*)(g_y + (size_t)(b * TT + trow) * CC + h * HD + dcol) = pr;
                }
            }
    }
}

// ------------------------- launch ---------------------------------------------
extern "C" void kernel_launch(void* const* d_in, const int* in_sizes, int n_in,
                              void* d_out, int out_size)
{
    (void)in_sizes; (void)n_in; (void)out_size;
    const float* x  = (const float*)d_in[0];
    const float* Wq = (const float*)d_in[1];
    const float* bq = (const float*)d_in[2];
    const float* Wk = (const float*)d_in[3];
    const float* bk = (const float*)d_in[4];
    const float* Wv = (const float*)d_in[5];
    const float* bv = (const float*)d_in[6];
    const float* Wo = (const float*)d_in[7];
    const float* bo = (const float*)d_in[8];
    float* out = (float*)d_out;

    cudaFuncSetAttribute(k_gemm, cudaFuncAttributeMaxDynamicSharedMemorySize, GSMEM);
    cudaFuncSetAttribute(k_att,  cudaFuncAttributeMaxDynamicSharedMemorySize, ATT_SMEM);

    k_conv_x  <<<(size_t)MM * CC / 1024, 256>>>(x);
    k_prepW   <<<dim3(32, 32, 4), dim3(32, 8)>>>(Wq, Wk, Wv, Wo, bq, bk, bv, bo);
    k_rope    <<<TT, 32>>>();
    k_gemm    <<<dim3(8, 64, 3), 256, GSMEM>>>(0, nullptr);   // q,k,v projections (+rope)
    k_att     <<<dim3(16, 64), 256, ATT_SMEM>>>();            // fused attention (q-tile 128)
    k_gemm    <<<dim3(8, 64, 1), 256, GSMEM>>>(3, out);       // output projection
}

// round 15
// speedup vs baseline: 1.1219x; 1.1219x over previous
#include <cuda_runtime.h>
#include <cuda_bf16.h>
#include <cstdint>
#include <math.h>

#define BB 4
#define TT 2048
#define CC 1024
#define HH 16
#define HD 64
#define BH (BB*HH)   /* 64 */
#define MM (BB*TT)   /* 8192 */

// ------------------------- scratch (static device globals; no allocs) ---------
__device__ __nv_bfloat16 g_xb[(size_t)MM*CC];          // x in bf16
__device__ __nv_bfloat16 g_WT[4][(size_t)CC*CC];       // Wq,Wk,Wv,Wo transposed [n][k] bf16
__device__ __nv_bfloat16 g_bias[4][CC];                // bq,bk,bv,bo bf16
__device__ __nv_bfloat16 g_q[(size_t)BH*TT*HD];        // [bh][t][d] post-rope bf16
__device__ __nv_bfloat16 g_k[(size_t)BH*TT*HD];
__device__ __nv_bfloat16 g_v[(size_t)BH*TT*HD];
__device__ __nv_bfloat16 g_S[(size_t)BH*TT*TT];        // bf16 scaled logits (lower-tri tiles)
__device__ __nv_bfloat16 g_y[(size_t)MM*CC];           // attention output bf16 [b*T+t][h*64+d]
__device__ float         g_cos[TT*(HD/2)];
__device__ float         g_sin[TT*(HD/2)];

// ------------------------- packed f32x2 primitives (sm_100a) ------------------
__device__ __forceinline__ uint64_t f32x2pk(float a, float b) {
    uint64_t r; asm("mov.b64 %0, {%1,%2};" : "=l"(r) : "f"(a), "f"(b)); return r;
}
__device__ __forceinline__ void f32x2upk(uint64_t v, float& a, float& b) {
    asm("mov.b64 {%0,%1}, %2;" : "=f"(a), "=f"(b) : "l"(v));
}
__device__ __forceinline__ uint64_t fma2(uint64_t a, uint64_t b, uint64_t c) {
    uint64_t d; asm("fma.rn.f32x2 %0,%1,%2,%3;" : "=l"(d) : "l"(a), "l"(b), "l"(c)); return d;
}
__device__ __forceinline__ uint64_t mul2(uint64_t a, uint64_t b) {
    uint64_t d; asm("mul.rn.f32x2 %0,%1,%2;" : "=l"(d) : "l"(a), "l"(b)); return d;
}
__device__ __forceinline__ uint64_t add2(uint64_t a, uint64_t b) {
    uint64_t d; asm("add.rn.f32x2 %0,%1,%2;" : "=l"(d) : "l"(a), "l"(b)); return d;
}

// Pairwise accurate exp: per-lane op sequence IDENTICAL to scalar exp_rn (R5-R13).
__device__ __forceinline__ void exp_rn2(float x0, float x1, float& o0, float& o1) {
    x0 = fmaxf(x0, -87.0f); x1 = fmaxf(x1, -87.0f);
    uint64_t X = f32x2pk(x0, x1);
    uint64_t T = fma2(X, f32x2pk(1.44269504088896341f, 1.44269504088896341f),
                         f32x2pk(0.5f, 0.5f));
    float t0, t1; f32x2upk(T, t0, t1);
    float mf0 = floorf(t0), mf1 = floorf(t1);
    uint64_t MF = f32x2pk(mf0, mf1);
    uint64_t R = fma2(MF, f32x2pk(-0.693359375f, -0.693359375f), X);
    R = fma2(MF, f32x2pk(2.12194440e-4f, 2.12194440e-4f), R);
    uint64_t P = f32x2pk(1.9875691500e-4f, 1.9875691500e-4f);
    P = fma2(P, R, f32x2pk(1.3981999507e-3f, 1.3981999507e-3f));
    P = fma2(P, R, f32x2pk(8.3334519073e-3f, 8.3334519073e-3f));
    P = fma2(P, R, f32x2pk(4.1665795894e-2f, 4.1665795894e-2f));
    P = fma2(P, R, f32x2pk(1.6666665459e-1f, 1.6666665459e-1f));
    P = fma2(P, R, f32x2pk(5.0000001201e-1f, 5.0000001201e-1f));
    uint64_t Y = fma2(P, mul2(R, R), R);
    Y = add2(Y, f32x2pk(1.0f, 1.0f));
    int mi0 = (int)mf0, mi1 = (int)mf1;
    uint64_t SC = f32x2pk(__int_as_float((mi0 + 127) << 23),
                          __int_as_float((mi1 + 127) << 23));
    Y = mul2(Y, SC);
    f32x2upk(Y, o0, o1);
}

// ------------------------- mma.sync m16n8k16 bf16 -----------------------------
__device__ __forceinline__ void mma_bf16(float c[4], const uint32_t a[4], const uint32_t b[2]) {
    asm volatile(
        "mma.sync.aligned.m16n8k16.row.col.f32.bf16.bf16.f32 "
        "{%0,%1,%2,%3}, {%4,%5,%6,%7}, {%8,%9}, {%0,%1,%2,%3};\n"
        : "+f"(c[0]), "+f"(c[1]), "+f"(c[2]), "+f"(c[3])
        : "r"(a[0]), "r"(a[1]), "r"(a[2]), "r"(a[3]), "r"(b[0]), "r"(b[1]));
}

__device__ __forceinline__ void ldsm_x4(uint32_t r[4], uint32_t addr) {
    asm volatile("ldmatrix.sync.aligned.m8n8.x4.shared.b16 {%0,%1,%2,%3}, [%4];"
                 : "=r"(r[0]), "=r"(r[1]), "=r"(r[2]), "=r"(r[3]) : "r"(addr));
}

// ------------------------- prep kernels ---------------------------------------
__global__ void k_conv_x(const float* __restrict__ x) {
    size_t i = ((size_t)blockIdx.x * 256 + threadIdx.x) * 4;
    float4 v = *(const float4*)(x + i);
    __nv_bfloat162 a, b;
    a.x = __float2bfloat16(v.x); a.y = __float2bfloat16(v.y);
    b.x = __float2bfloat16(v.z); b.y = __float2bfloat16(v.w);
    *(__nv_bfloat162*)(g_xb + i)     = a;
    *(__nv_bfloat162*)(g_xb + i + 2) = b;
}

__global__ void k_prepW(const float* __restrict__ Wq, const float* __restrict__ Wk,
                        const float* __restrict__ Wv, const float* __restrict__ Wo,
                        const float* __restrict__ bq, const float* __restrict__ bk,
                        const float* __restrict__ bv, const float* __restrict__ bo) {
    const float* W = (blockIdx.z == 0) ? Wq : (blockIdx.z == 1) ? Wk : (blockIdx.z == 2) ? Wv : Wo;
    __shared__ float tile[32][33];
    int n0 = blockIdx.x * 32, k0 = blockIdx.y * 32;
    for (int jj = threadIdx.y; jj < 32; jj += 8)
        tile[jj][threadIdx.x] = W[(size_t)(k0 + jj) * CC + n0 + threadIdx.x];
    if (blockIdx.y == 0 && threadIdx.y == 0) {
        const float* p = (blockIdx.z == 0) ? bq : (blockIdx.z == 1) ? bk
                       : (blockIdx.z == 2) ? bv : bo;
        g_bias[blockIdx.z][n0 + threadIdx.x] = __float2bfloat16(p[n0 + threadIdx.x]);
    }
    __syncthreads();
    for (int jj = threadIdx.y; jj < 32; jj += 8)
        g_WT[blockIdx.z][(size_t)(n0 + jj) * CC + k0 + threadIdx.x] =
            __float2bfloat16(tile[threadIdx.x][jj]);
}

__global__ void k_rope() {
    int t = blockIdx.x, j = threadIdx.x;                 // j in 0..31
    double e = (double)(2 * j) / 64.0;
    float p32 = (float)pow(10000.0, e);
    float inv = __fdiv_rn(1.0f, p32);
    float ang = __fmul_rn((float)t, inv);
    g_cos[t * (HD/2) + j] = (float)cos((double)ang);
    g_sin[t * (HD/2) + j] = (float)sin((double)ang);
}

// ------------------------- GEMM: x@W (+bias, rope) / y@Wo --------------------
#define GSTAGE 36864
#define GSMEM  (2*GSTAGE)

__global__ __launch_bounds__(256) void k_gemm(int mode_base, float* __restrict__ outF)
{
    extern __shared__ unsigned char gsm[];
    const int mode = mode_base + blockIdx.z;
    const __nv_bfloat16* __restrict__ A  = (mode < 3) ? g_xb : g_y;
    const __nv_bfloat16* __restrict__ Bt = g_WT[mode];
    const __nv_bfloat16* __restrict__ bs = g_bias[mode];
    const int m0 = blockIdx.y * 128;
    const int n0 = blockIdx.x * 128;

    const int tid = threadIdx.x;
    const int wid = tid >> 5, lane = tid & 31;
    const int g = lane >> 2, t4 = lane & 3;
    const int wm = wid & 3, wn = wid >> 2;
    const int lb = lane >> 3, lr = lane & 7;

    float acc[16][4];
    #pragma unroll
    for (int i = 0; i < 16; i++) { acc[i][0] = acc[i][1] = acc[i][2] = acc[i][3] = 0.f; }

    {
        __nv_bfloat16* sA = (__nv_bfloat16*)gsm;
        __nv_bfloat16* sB = (__nv_bfloat16*)(gsm + GSTAGE / 2);
        #pragma unroll
        for (int rep = 0; rep < 4; rep++) {
            int i = tid + rep * 256;
            int row = i >> 3, cg = i & 7;
            uint32_t da = (uint32_t)__cvta_generic_to_shared(sA + row * 72 + cg * 8);
            uint32_t db = (uint32_t)__cvta_generic_to_shared(sB + row * 72 + cg * 8);
            asm volatile("cp.async.cg.shared.global [%0], [%1], 16;\n"
                         :: "r"(da), "l"(A  + (size_t)(m0 + row) * CC + cg * 8));
            asm volatile("cp.async.cg.shared.global [%0], [%1], 16;\n"
                         :: "r"(db), "l"(Bt + (size_t)(n0 + row) * CC + cg * 8));
        }
        asm volatile("cp.async.commit_group;\n");
    }

    for (int it = 0; it < 16; it++) {
        asm volatile("cp.async.wait_group 0;\n");
        __syncthreads();
        if (it + 1 < 16) {
            int k0 = (it + 1) * 64;
            unsigned char* stg = gsm + ((it + 1) & 1) * GSTAGE;
            __nv_bfloat16* sA = (__nv_bfloat16*)stg;
            __nv_bfloat16* sB = (__nv_bfloat16*)(stg + GSTAGE / 2);
            #pragma unroll
            for (int rep = 0; rep < 4; rep++) {
                int i = tid + rep * 256;
                int row = i >> 3, cg = i & 7;
                uint32_t da = (uint32_t)__cvta_generic_to_shared(sA + row * 72 + cg * 8);
                uint32_t db = (uint32_t)__cvta_generic_to_shared(sB + row * 72 + cg * 8);
                asm volatile("cp.async.cg.shared.global [%0], [%1], 16;\n"
                             :: "r"(da), "l"(A  + (size_t)(m0 + row) * CC + k0 + cg * 8));
                asm volatile("cp.async.cg.shared.global [%0], [%1], 16;\n"
                             :: "r"(db), "l"(Bt + (size_t)(n0 + row) * CC + k0 + cg * 8));
            }
            asm volatile("cp.async.commit_group;\n");
        }
        const __nv_bfloat16* sA = (const __nv_bfloat16*)(gsm + (it & 1) * GSTAGE);
        const __nv_bfloat16* sB = (const __nv_bfloat16*)(gsm + (it & 1) * GSTAGE + GSTAGE / 2);
        #pragma unroll
        for (int ks = 0; ks < 64; ks += 16) {
            uint32_t af[2][4];
            #pragma unroll
            for (int mt = 0; mt < 2; mt++) {
                int row = wm * 32 + mt * 16 + (lb & 1) * 8 + lr;
                int col = ks + (lb >> 1) * 8;
                ldsm_x4(af[mt], (uint32_t)__cvta_generic_to_shared(sA + row * 72 + col));
            }
            uint32_t bfr[8][2];
            #pragma unroll
            for (int p = 0; p < 4; p++) {
                int row = wn * 64 + (2 * p + (lb >> 1)) * 8 + lr;
                int col = ks + (lb & 1) * 8;
                uint32_t q[4];
                ldsm_x4(q, (uint32_t)__cvta_generic_to_shared(sB + row * 72 + col));
                bfr[2 * p][0] = q[0]; bfr[2 * p][1] = q[1];
                bfr[2 * p + 1][0] = q[2]; bfr[2 * p + 1][1] = q[3];
            }
            #pragma unroll
            for (int mt = 0; mt < 2; mt++)
                #pragma unroll
                for (int nt = 0; nt < 8; nt++)
                    mma_bf16(acc[mt * 8 + nt], af[mt], bfr[nt]);
        }
    }

    #pragma unroll
    for (int mt = 0; mt < 2; mt++) {
        #pragma unroll
        for (int nt = 0; nt < 8; nt++) {
            float* c = acc[mt * 8 + nt];
            int col = n0 + wn * 64 + nt * 8 + 2 * t4;
            int r0  = m0 + wm * 32 + mt * 16 + g;
            #pragma unroll
            for (int hf = 0; hf < 2; hf++) {
                int row = r0 + hf * 8;
                __nv_bfloat16 eb = __hadd(__float2bfloat16(c[hf * 2 + 0]), bs[col]);
                __nv_bfloat16 ob = __hadd(__float2bfloat16(c[hf * 2 + 1]), bs[col + 1]);
                if (mode == 3) {
                    outF[(size_t)row * CC + col]     = __bfloat162float(eb);
                    outF[(size_t)row * CC + col + 1] = __bfloat162float(ob);
                } else {
                    int b = row >> 11, t = row & (TT - 1);
                    int h = col >> 6,  d = col & 63;
                    size_t oidx = ((size_t)(b * HH + h) * TT + t) * HD + d;
                    __nv_bfloat162 pr;
                    if (mode <= 1) {
                        int j = d >> 1;
                        float cth = g_cos[t * (HD/2) + j], sth = g_sin[t * (HD/2) + j];
                        float ef = __bfloat162float(eb), of = __bfloat162float(ob);
                        float re = __fsub_rn(__fmul_rn(ef, cth), __fmul_rn(of, sth));
                        float ro = __fadd_rn(__fmul_rn(ef, sth), __fmul_rn(of, cth));
                        pr.x = __float2bfloat16(re);
                        pr.y = __float2bfloat16(ro);
                    } else {
                        pr.x = eb; pr.y = ob;
                    }
                    __nv_bfloat16* outp = (mode == 0) ? g_q : (mode == 1) ? g_k : g_v;
                    *(__nv_bfloat162*)(outp + oidx) = pr;
                }
            }
        }
    }
}

// --------- fused attention (R13 structure): q-tile 64, 16x32 warp tiles -------
__global__ __launch_bounds__(256) void k_att()
{
    __shared__ __align__(16) unsigned char buf[36864];
    __shared__ float sMax[2][64];
    __shared__ float sMfin[64];
    __shared__ float sLfin[64];

    const int qt = gridDim.x - 1 - blockIdx.x;           // heavy tiles first
    const int bh = blockIdx.y;
    const int q0 = qt * 64;
    const __nv_bfloat16* __restrict__ Q = g_q + (size_t)bh * TT * HD;
    const __nv_bfloat16* __restrict__ K = g_k + (size_t)bh * TT * HD;
    const __nv_bfloat16* __restrict__ V = g_v + (size_t)bh * TT * HD;

    const int tid = threadIdx.x;
    const int wid = tid >> 5, lane = tid & 31;
    const int g = lane >> 2, t4 = lane & 3;
    const int wm = wid & 3, wn = wid >> 2;
    const int r0 = wm * 16 + g;
    const int lb = lane >> 3, lr = lane & 7;

    // ===================== phase A: S = bf16(QK^T)*0.125, max, l ==============
    {
        __nv_bfloat16* sQ = (__nv_bfloat16*)buf;
        #pragma unroll
        for (int rep = 0; rep < 2; rep++) {
            int i = tid + rep * 256;
            int row = i >> 3, cg = i & 7;
            *(uint4*)&sQ[row * 72 + cg * 8] = *(const uint4*)(Q + (size_t)(q0 + row) * HD + cg * 8);
        }
        #pragma unroll
        for (int rep = 0; rep < 2; rep++) {
            int i = tid + rep * 256;
            int row = i >> 3, cg = i & 7;
            uint32_t dst = (uint32_t)__cvta_generic_to_shared(buf + 9216 + (row * 72 + cg * 8) * 2);
            asm volatile("cp.async.cg.shared.global [%0], [%1], 16;\n"
                         :: "r"(dst), "l"(K + (size_t)row * HD + cg * 8));
        }
        asm volatile("cp.async.commit_group;\n");

        const int qg0 = q0 + r0, qg1 = qg0 + 8;
        float rmax0 = -INFINITY, rmax1 = -INFINITY;

        for (int kt = 0; kt <= qt; kt++) {
            asm volatile("cp.async.wait_group 0;\n");
            __syncthreads();
            if (kt < qt) {
                unsigned char* dstb = buf + 9216 + ((kt + 1) & 1) * 9216;
                #pragma unroll
                for (int rep = 0; rep < 2; rep++) {
                    int i = tid + rep * 256;
                    int row = i >> 3, cg = i & 7;
                    uint32_t dst = (uint32_t)__cvta_generic_to_shared(dstb + (row * 72 + cg * 8) * 2);
                    asm volatile("cp.async.cg.shared.global [%0], [%1], 16;\n"
                                 :: "r"(dst), "l"(K + (size_t)((kt + 1) * 64 + row) * HD + cg * 8));
                }
                asm volatile("cp.async.commit_group;\n");
            }
            const __nv_bfloat16* sKb = (const __nv_bfloat16*)(buf + 9216 + (kt & 1) * 9216);
            float acc[4][4] = {};
            #pragma unroll
            for (int ks = 0; ks < 64; ks += 16) {
                uint32_t af[4];
                {
                    int row = wm * 16 + (lb & 1) * 8 + lr;
                    int col = ks + (lb >> 1) * 8;
                    ldsm_x4(af, (uint32_t)__cvta_generic_to_shared(sQ + row * 72 + col));
                }
                uint32_t kf[4][2];
                #pragma unroll
                for (int p = 0; p < 2; p++) {
                    int row = wn * 32 + (2 * p + (lb >> 1)) * 8 + lr;
                    int col = ks + (lb & 1) * 8;
                    uint32_t q4[4];
                    ldsm_x4(q4, (uint32_t)__cvta_generic_to_shared(sKb + row * 72 + col));
                    kf[2 * p][0] = q4[0]; kf[2 * p][1] = q4[1];
                    kf[2 * p + 1][0] = q4[2]; kf[2 * p + 1][1] = q4[3];
                }
                #pragma unroll
                for (int nt = 0; nt < 4; nt++)
                    mma_bf16(acc[nt], af, kf[nt]);
            }
            #pragma unroll
            for (int nt = 0; nt < 4; nt++) {
                int cl = wn * 32 + nt * 8 + 2 * t4;
                int kc = kt * 64 + cl;
                {
                    float s0 = __fmul_rn(__bfloat162float(__float2bfloat16(acc[nt][0])), 0.125f);
                    float s1 = __fmul_rn(__bfloat162float(__float2bfloat16(acc[nt][1])), 0.125f);
                    if (kc     <= qg0) rmax0 = fmaxf(rmax0, s0);
                    if (kc + 1 <= qg0) rmax0 = fmaxf(rmax0, s1);
                    __nv_bfloat162 pr; pr.x = __float2bfloat16(s0); pr.y = __float2bfloat16(s1);
                    *(__nv_bfloat162*)(g_S + (size_t)(bh * TT + qg0) * TT + kc) = pr;
                }
                {
                    float s0 = __fmul_rn(__bfloat162float(__float2bfloat16(acc[nt][2])), 0.125f);
                    float s1 = __fmul_rn(__bfloat162float(__float2bfloat16(acc[nt][3])), 0.125f);
                    if (kc     <= qg1) rmax1 = fmaxf(rmax1, s0);
                    if (kc + 1 <= qg1) rmax1 = fmaxf(rmax1, s1);
                    __nv_bfloat162 pr; pr.x = __float2bfloat16(s0); pr.y = __float2bfloat16(s1);
                    *(__nv_bfloat162*)(g_S + (size_t)(bh * TT + qg1) * TT + kc) = pr;
                }
            }
        }
        rmax0 = fmaxf(rmax0, __shfl_xor_sync(0xffffffffu, rmax0, 1));
        rmax0 = fmaxf(rmax0, __shfl_xor_sync(0xffffffffu, rmax0, 2));
        rmax1 = fmaxf(rmax1, __shfl_xor_sync(0xffffffffu, rmax1, 1));
        rmax1 = fmaxf(rmax1, __shfl_xor_sync(0xffffffffu, rmax1, 2));
        if (t4 == 0) {
            sMax[wn][wm * 16 + g]     = rmax0;
            sMax[wn][wm * 16 + g + 8] = rmax1;
        }
        __syncthreads();
        if (tid < 64) sMfin[tid] = fmaxf(sMax[0][tid], sMax[1][tid]);
        __syncthreads();

        // V tile 0 prestage (sK buffers dead) — lands during the l-pass.
        #pragma unroll
        for (int rep = 0; rep < 2; rep++) {
            int i = tid + rep * 256;
            int row = i >> 3, cg = i & 7;
            uint32_t dst = (uint32_t)__cvta_generic_to_shared(buf + 18432 + (row * 72 + cg * 8) * 2);
            asm volatile("cp.async.cg.shared.global [%0], [%1], 16;\n"
                         :: "r"(dst), "l"(V + (size_t)row * HD + cg * 8));
        }
        asm volatile("cp.async.commit_group;\n");

        // l-pass: 4 independent add chains (2 packed f32x2 accumulators).
        // Masked elements add exact 0.0f (x+0 == x in RN for e>0).
        {
            const int prow = tid >> 2;
            const int pcb  = (tid & 3) * 16;
            const int qgp  = q0 + prow;
            const float mrow = sMfin[prow];
            const __nv_bfloat16* __restrict__ Srow = g_S + (size_t)(bh * TT + qgp) * TT;
            uint64_t L0 = f32x2pk(0.f, 0.f), L1 = f32x2pk(0.f, 0.f);
            uint4 c0 = *(const uint4*)(Srow + pcb);
            uint4 c1 = *(const uint4*)(Srow + pcb + 8);
            for (int kt = 0; kt <= qt; kt++) {
                uint4 n0v, n1v;
                if (kt < qt) {
                    n0v = *(const uint4*)(Srow + (kt + 1) * 64 + pcb);
                    n1v = *(const uint4*)(Srow + (kt + 1) * 64 + pcb + 8);
                }
                __nv_bfloat16 hv[16];
                *(uint4*)&hv[0] = c0;
                *(uint4*)&hv[8] = c1;
                #pragma unroll
                for (int j = 0; j < 16; j += 4) {
                    int col = kt * 64 + pcb + j;
                    float e0, e1, e2, e3;
                    exp_rn2(__fsub_rn(__bfloat162float(hv[j]),     mrow),
                            __fsub_rn(__bfloat162float(hv[j + 1]), mrow), e0, e1);
                    exp_rn2(__fsub_rn(__bfloat162float(hv[j + 2]), mrow),
                            __fsub_rn(__bfloat162float(hv[j + 3]), mrow), e2, e3);
                    e0 = (col     <= qgp) ? e0 : 0.f;
                    e1 = (col + 1 <= qgp) ? e1 : 0.f;
                    e2 = (col + 2 <= qgp) ? e2 : 0.f;
                    e3 = (col + 3 <= qgp) ? e3 : 0.f;
                    L0 = add2(L0, f32x2pk(e0, e1));
                    L1 = add2(L1, f32x2pk(e2, e3));
                }
                c0 = n0v; c1 = n1v;
            }
            float a0, a1, b0, b1;
            f32x2upk(L0, a0, a1);
            f32x2upk(L1, b0, b1);
            float lp = __fadd_rn(__fadd_rn(__fadd_rn(a0, a1), b0), b1);
            lp = __fadd_rn(lp, __shfl_xor_sync(0xffffffffu, lp, 1));
            lp = __fadd_rn(lp, __shfl_xor_sync(0xffffffffu, lp, 2));
            if ((tid & 3) == 0) sLfin[qgp - q0] = lp;
        }
    }
    __syncthreads();   // sLfin ready; phase A smem (sQ/sK) dead from here

    // ===================== phase B: p = bf16(softmax), y = P@V^T ===============
    {
        const int prow = tid >> 2;
        const int pcb  = (tid & 3) * 16;
        const int qgp  = q0 + prow;
        const float mrow = sMfin[prow];
        const float lrow = sLfin[prow];
        const __nv_bfloat16* __restrict__ Srow = g_S + (size_t)(bh * TT + qgp) * TT;

        float acc[4][4] = {};
        const int l16 = lane & 15;

        uint4 s0 = *(const uint4*)(Srow + pcb);
        uint4 s1 = *(const uint4*)(Srow + pcb + 8);

        for (int kt = 0; kt <= qt; kt++) {
            const int bsel = kt & 1;
            __nv_bfloat16* sPb = (__nv_bfloat16*)(buf + bsel * 9216);
            const __nv_bfloat16* sVb = (const __nv_bfloat16*)(buf + 18432 + bsel * 9216);
            {
                __nv_bfloat16 hv[16];
                *(uint4*)&hv[0] = s0;
                *(uint4*)&hv[8] = s1;
                #pragma unroll
                for (int j = 0; j < 16; j += 2) {
                    int col = kt * 64 + pcb + j;
                    float e0, e1;
                    exp_rn2(__fsub_rn(__bfloat162float(hv[j]),     mrow),
                            __fsub_rn(__bfloat162float(hv[j + 1]), mrow), e0, e1);
                    __nv_bfloat162 pr;
                    pr.x = (col     <= qgp) ? __float2bfloat16(__fdiv_rn(e0, lrow))
                                            : __float2bfloat16(0.f);
                    pr.y = (col + 1 <= qgp) ? __float2bfloat16(__fdiv_rn(e1, lrow))
                                            : __float2bfloat16(0.f);
                    *(__nv_bfloat162*)&sPb[prow * 72 + pcb + j] = pr;
                }
            }
            asm volatile("cp.async.wait_group 0;\n");
            __syncthreads();
            if (kt < qt) {
                unsigned char* dstb = buf + 18432 + ((kt + 1) & 1) * 9216;
                #pragma unroll
                for (int rep = 0; rep < 2; rep++) {
                    int i = tid + rep * 256;
                    int row = i >> 3, cg = i & 7;
                    uint32_t dst = (uint32_t)__cvta_generic_to_shared(dstb + (row * 72 + cg * 8) * 2);
                    asm volatile("cp.async.cg.shared.global [%0], [%1], 16;\n"
                                 :: "r"(dst), "l"(V + (size_t)((kt + 1) * 64 + row) * HD + cg * 8));
                }
                asm volatile("cp.async.commit_group;\n");
                s0 = *(const uint4*)(Srow + (kt + 1) * 64 + pcb);
                s1 = *(const uint4*)(Srow + (kt + 1) * 64 + pcb + 8);
            }
            #pragma unroll
            for (int ks = 0; ks < 64; ks += 16) {
                uint32_t af[4];
                {
                    int row = wm * 16 + (lb & 1) * 8 + lr;
                    int col = ks + (lb >> 1) * 8;
                    ldsm_x4(af, (uint32_t)__cvta_generic_to_shared(sPb + row * 72 + col));
                }
                #pragma unroll
                for (int nt = 0; nt < 4; nt++) {
                    int n0c = wn * 32 + nt * 8;
                    uint32_t vaddr = (uint32_t)__cvta_generic_to_shared(
                        sVb + (size_t)(ks + l16) * 72 + n0c);
                    uint32_t b2[2];
                    asm volatile(
                        "ldmatrix.sync.aligned.m8n8.x2.trans.shared.b16 {%0,%1}, [%2];"
                        : "=r"(b2[0]), "=r"(b2[1]) : "r"(vaddr));
                    mma_bf16(acc[nt], af, b2);
                }
            }
        }

        const int b = bh >> 4, h = bh & 15;
        #pragma unroll
        for (int nt = 0; nt < 4; nt++) {
            int dcol = wn * 32 + nt * 8 + 2 * t4;
            #pragma unroll
            for (int hf = 0; hf < 2; hf++) {
                int trow = q0 + r0 + hf * 8;
                __nv_bfloat162 pr;
                pr.x = __float2bfloat16(acc[nt][hf * 2 + 0]);
                pr.y = __float2bfloat16(acc[nt][hf * 2 + 1]);
                *(__nv_bfloat162*)(g_y + (size_t)(b * TT + trow) * CC + h * HD + dcol) = pr;
            }
        }
    }
}

// ------------------------- launch ---------------------------------------------
extern "C" void kernel_launch(void* const* d_in, const int* in_sizes, int n_in,
                              void* d_out, int out_size)
{
    (void)in_sizes; (void)n_in; (void)out_size;
    const float* x  = (const float*)d_in[0];
    const float* Wq = (const float*)d_in[1];
    const float* bq = (const float*)d_in[2];
    const float* Wk = (const float*)d_in[3];
    const float* bk = (const float*)d_in[4];
    const float* Wv = (const float*)d_in[5];
    const float* bv = (const float*)d_in[6];
    const float* Wo = (const float*)d_in[7];
    const float* bo = (const float*)d_in[8];
    float* out = (float*)d_out;

    cudaFuncSetAttribute(k_gemm, cudaFuncAttributeMaxDynamicSharedMemorySize, GSMEM);

    k_conv_x  <<<(size_t)MM * CC / 1024, 256>>>(x);
    k_prepW   <<<dim3(32, 32, 4), dim3(32, 8)>>>(Wq, Wk, Wv, Wo, bq, bk, bv, bo);
    k_rope    <<<TT, 32>>>();
    k_gemm    <<<dim3(8, 64, 3), 256, GSMEM>>>(0, nullptr);   // q,k,v projections (+rope)
    k_att     <<<dim3(32, 64), 256>>>();                      // fused attention
    k_gemm    <<<dim3(8, 64, 1), 256, GSMEM>>>(3, out);       // output projection
}

// round 16
// speedup vs baseline: 1.1309x; 1.0080x over previous
#include <cuda_runtime.h>
#include <cuda_bf16.h>
#include <cstdint>
#include <math.h>

#define BB 4
#define TT 2048
#define CC 1024
#define HH 16
#define HD 64
#define BH (BB*HH)   /* 64 */
#define MM (BB*TT)   /* 8192 */

// ------------------------- scratch (static device globals; no allocs) ---------
__device__ __nv_bfloat16 g_xb[(size_t)MM*CC];          // x in bf16
__device__ __nv_bfloat16 g_WT[4][(size_t)CC*CC];       // Wq,Wk,Wv,Wo transposed [n][k] bf16
__device__ __nv_bfloat16 g_bias[4][CC];                // bq,bk,bv,bo bf16
__device__ __nv_bfloat16 g_q[(size_t)BH*TT*HD];        // [bh][t][d] post-rope bf16
__device__ __nv_bfloat16 g_k[(size_t)BH*TT*HD];
__device__ __nv_bfloat16 g_v[(size_t)BH*TT*HD];
__device__ __nv_bfloat16 g_S[(size_t)BH*TT*TT];        // bf16 scaled logits (lower-tri tiles)
__device__ __nv_bfloat16 g_y[(size_t)MM*CC];           // attention output bf16 [b*T+t][h*64+d]
__device__ float         g_cos[TT*(HD/2)];
__device__ float         g_sin[TT*(HD/2)];

// ------------------------- packed f32x2 primitives (sm_100a) ------------------
__device__ __forceinline__ uint64_t f32x2pk(float a, float b) {
    uint64_t r; asm("mov.b64 %0, {%1,%2};" : "=l"(r) : "f"(a), "f"(b)); return r;
}
__device__ __forceinline__ void f32x2upk(uint64_t v, float& a, float& b) {
    asm("mov.b64 {%0,%1}, %2;" : "=f"(a), "=f"(b) : "l"(v));
}
__device__ __forceinline__ uint64_t fma2(uint64_t a, uint64_t b, uint64_t c) {
    uint64_t d; asm("fma.rn.f32x2 %0,%1,%2,%3;" : "=l"(d) : "l"(a), "l"(b), "l"(c)); return d;
}
__device__ __forceinline__ uint64_t mul2(uint64_t a, uint64_t b) {
    uint64_t d; asm("mul.rn.f32x2 %0,%1,%2;" : "=l"(d) : "l"(a), "l"(b)); return d;
}
__device__ __forceinline__ uint64_t add2(uint64_t a, uint64_t b) {
    uint64_t d; asm("add.rn.f32x2 %0,%1,%2;" : "=l"(d) : "l"(a), "l"(b)); return d;
}

// Pairwise accurate exp: per-lane op sequence IDENTICAL to scalar exp_rn (R5-R13).
__device__ __forceinline__ void exp_rn2(float x0, float x1, float& o0, float& o1) {
    x0 = fmaxf(x0, -87.0f); x1 = fmaxf(x1, -87.0f);
    uint64_t X = f32x2pk(x0, x1);
    uint64_t T = fma2(X, f32x2pk(1.44269504088896341f, 1.44269504088896341f),
                         f32x2pk(0.5f, 0.5f));
    float t0, t1; f32x2upk(T, t0, t1);
    float mf0 = floorf(t0), mf1 = floorf(t1);
    uint64_t MF = f32x2pk(mf0, mf1);
    uint64_t R = fma2(MF, f32x2pk(-0.693359375f, -0.693359375f), X);
    R = fma2(MF, f32x2pk(2.12194440e-4f, 2.12194440e-4f), R);
    uint64_t P = f32x2pk(1.9875691500e-4f, 1.9875691500e-4f);
    P = fma2(P, R, f32x2pk(1.3981999507e-3f, 1.3981999507e-3f));
    P = fma2(P, R, f32x2pk(8.3334519073e-3f, 8.3334519073e-3f));
    P = fma2(P, R, f32x2pk(4.1665795894e-2f, 4.1665795894e-2f));
    P = fma2(P, R, f32x2pk(1.6666665459e-1f, 1.6666665459e-1f));
    P = fma2(P, R, f32x2pk(5.0000001201e-1f, 5.0000001201e-1f));
    uint64_t Y = fma2(P, mul2(R, R), R);
    Y = add2(Y, f32x2pk(1.0f, 1.0f));
    int mi0 = (int)mf0, mi1 = (int)mf1;
    uint64_t SC = f32x2pk(__int_as_float((mi0 + 127) << 23),
                          __int_as_float((mi1 + 127) << 23));
    Y = mul2(Y, SC);
    f32x2upk(Y, o0, o1);
}

// ------------------------- mma.sync m16n8k16 bf16 -----------------------------
__device__ __forceinline__ void mma_bf16(float c[4], const uint32_t a[4], const uint32_t b[2]) {
    asm volatile(
        "mma.sync.aligned.m16n8k16.row.col.f32.bf16.bf16.f32 "
        "{%0,%1,%2,%3}, {%4,%5,%6,%7}, {%8,%9}, {%0,%1,%2,%3};\n"
        : "+f"(c[0]), "+f"(c[1]), "+f"(c[2]), "+f"(c[3])
        : "r"(a[0]), "r"(a[1]), "r"(a[2]), "r"(a[3]), "r"(b[0]), "r"(b[1]));
}

__device__ __forceinline__ void ldsm_x4(uint32_t r[4], uint32_t addr) {
    asm volatile("ldmatrix.sync.aligned.m8n8.x4.shared.b16 {%0,%1,%2,%3}, [%4];"
                 : "=r"(r[0]), "=r"(r[1]), "=r"(r[2]), "=r"(r[3]) : "r"(addr));
}

// ------------------------- prep kernels ---------------------------------------
__global__ void k_conv_x(const float* __restrict__ x) {
    size_t i = ((size_t)blockIdx.x * 256 + threadIdx.x) * 4;
    float4 v = *(const float4*)(x + i);
    __nv_bfloat162 a, b;
    a.x = __float2bfloat16(v.x); a.y = __float2bfloat16(v.y);
    b.x = __float2bfloat16(v.z); b.y = __float2bfloat16(v.w);
    *(__nv_bfloat162*)(g_xb + i)     = a;
    *(__nv_bfloat162*)(g_xb + i + 2) = b;
}

__global__ void k_prepW(const float* __restrict__ Wq, const float* __restrict__ Wk,
                        const float* __restrict__ Wv, const float* __restrict__ Wo,
                        const float* __restrict__ bq, const float* __restrict__ bk,
                        const float* __restrict__ bv, const float* __restrict__ bo) {
    const float* W = (blockIdx.z == 0) ? Wq : (blockIdx.z == 1) ? Wk : (blockIdx.z == 2) ? Wv : Wo;
    __shared__ float tile[32][33];
    int n0 = blockIdx.x * 32, k0 = blockIdx.y * 32;
    for (int jj = threadIdx.y; jj < 32; jj += 8)
        tile[jj][threadIdx.x] = W[(size_t)(k0 + jj) * CC + n0 + threadIdx.x];
    if (blockIdx.y == 0 && threadIdx.y == 0) {
        const float* p = (blockIdx.z == 0) ? bq : (blockIdx.z == 1) ? bk
                       : (blockIdx.z == 2) ? bv : bo;
        g_bias[blockIdx.z][n0 + threadIdx.x] = __float2bfloat16(p[n0 + threadIdx.x]);
    }
    __syncthreads();
    for (int jj = threadIdx.y; jj < 32; jj += 8)
        g_WT[blockIdx.z][(size_t)(n0 + jj) * CC + k0 + threadIdx.x] =
            __float2bfloat16(tile[threadIdx.x][jj]);
}

__global__ void k_rope() {
    int t = blockIdx.x, j = threadIdx.x;                 // j in 0..31
    double e = (double)(2 * j) / 64.0;
    float p32 = (float)pow(10000.0, e);
    float inv = __fdiv_rn(1.0f, p32);
    float ang = __fmul_rn((float)t, inv);
    g_cos[t * (HD/2) + j] = (float)cos((double)ang);
    g_sin[t * (HD/2) + j] = (float)sin((double)ang);
}

// ------------------------- GEMM: x@W (+bias, rope) / y@Wo --------------------
// 128x128 tile, k-tile 64, cp.async 3-stage ring, ldmatrix fragment loads.
#define GSTAGE 36864
#define GSMEM  (3*GSTAGE)

__global__ __launch_bounds__(256) void k_gemm(int mode_base, float* __restrict__ outF)
{
    extern __shared__ unsigned char gsm[];
    const int mode = mode_base + blockIdx.z;
    const __nv_bfloat16* __restrict__ A  = (mode < 3) ? g_xb : g_y;
    const __nv_bfloat16* __restrict__ Bt = g_WT[mode];
    const __nv_bfloat16* __restrict__ bs = g_bias[mode];
    const int m0 = blockIdx.y * 128;
    const int n0 = blockIdx.x * 128;

    const int tid = threadIdx.x;
    const int wid = tid >> 5, lane = tid & 31;
    const int g = lane >> 2, t4 = lane & 3;
    const int wm = wid & 3, wn = wid >> 2;
    const int lb = lane >> 3, lr = lane & 7;

    float acc[16][4];
    #pragma unroll
    for (int i = 0; i < 16; i++) { acc[i][0] = acc[i][1] = acc[i][2] = acc[i][3] = 0.f; }

    // prologue: prefetch stages 0 and 1
    #pragma unroll
    for (int pre = 0; pre < 2; pre++) {
        int k0 = pre * 64;
        __nv_bfloat16* sA = (__nv_bfloat16*)(gsm + pre * GSTAGE);
        __nv_bfloat16* sB = (__nv_bfloat16*)(gsm + pre * GSTAGE + GSTAGE / 2);
        #pragma unroll
        for (int rep = 0; rep < 4; rep++) {
            int i = tid + rep * 256;
            int row = i >> 3, cg = i & 7;
            uint32_t da = (uint32_t)__cvta_generic_to_shared(sA + row * 72 + cg * 8);
            uint32_t db = (uint32_t)__cvta_generic_to_shared(sB + row * 72 + cg * 8);
            asm volatile("cp.async.cg.shared.global [%0], [%1], 16;\n"
                         :: "r"(da), "l"(A  + (size_t)(m0 + row) * CC + k0 + cg * 8));
            asm volatile("cp.async.cg.shared.global [%0], [%1], 16;\n"
                         :: "r"(db), "l"(Bt + (size_t)(n0 + row) * CC + k0 + cg * 8));
        }
        asm volatile("cp.async.commit_group;\n");
    }

    for (int it = 0; it < 16; it++) {
        if (it < 14) { asm volatile("cp.async.wait_group 1;\n"); }
        else         { asm volatile("cp.async.wait_group 0;\n"); }
        __syncthreads();
        if (it + 2 < 16) {
            int k0 = (it + 2) * 64;
            unsigned char* stg = gsm + ((it + 2) % 3) * GSTAGE;
            __nv_bfloat16* sA = (__nv_bfloat16*)stg;
            __nv_bfloat16* sB = (__nv_bfloat16*)(stg + GSTAGE / 2);
            #pragma unroll
            for (int rep = 0; rep < 4; rep++) {
                int i = tid + rep * 256;
                int row = i >> 3, cg = i & 7;
                uint32_t da = (uint32_t)__cvta_generic_to_shared(sA + row * 72 + cg * 8);
                uint32_t db = (uint32_t)__cvta_generic_to_shared(sB + row * 72 + cg * 8);
                asm volatile("cp.async.cg.shared.global [%0], [%1], 16;\n"
                             :: "r"(da), "l"(A  + (size_t)(m0 + row) * CC + k0 + cg * 8));
                asm volatile("cp.async.cg.shared.global [%0], [%1], 16;\n"
                             :: "r"(db), "l"(Bt + (size_t)(n0 + row) * CC + k0 + cg * 8));
            }
            asm volatile("cp.async.commit_group;\n");
        }
        const __nv_bfloat16* sA = (const __nv_bfloat16*)(gsm + (it % 3) * GSTAGE);
        const __nv_bfloat16* sB = (const __nv_bfloat16*)(gsm + (it % 3) * GSTAGE + GSTAGE / 2);
        #pragma unroll
        for (int ks = 0; ks < 64; ks += 16) {
            uint32_t af[2][4];
            #pragma unroll
            for (int mt = 0; mt < 2; mt++) {
                int row = wm * 32 + mt * 16 + (lb & 1) * 8 + lr;
                int col = ks + (lb >> 1) * 8;
                ldsm_x4(af[mt], (uint32_t)__cvta_generic_to_shared(sA + row * 72 + col));
            }
            uint32_t bfr[8][2];
            #pragma unroll
            for (int p = 0; p < 4; p++) {
                int row = wn * 64 + (2 * p + (lb >> 1)) * 8 + lr;
                int col = ks + (lb & 1) * 8;
                uint32_t q[4];
                ldsm_x4(q, (uint32_t)__cvta_generic_to_shared(sB + row * 72 + col));
                bfr[2 * p][0] = q[0]; bfr[2 * p][1] = q[1];
                bfr[2 * p + 1][0] = q[2]; bfr[2 * p + 1][1] = q[3];
            }
            #pragma unroll
            for (int mt = 0; mt < 2; mt++)
                #pragma unroll
                for (int nt = 0; nt < 8; nt++)
                    mma_bf16(acc[mt * 8 + nt], af[mt], bfr[nt]);
        }
    }

    #pragma unroll
    for (int mt = 0; mt < 2; mt++) {
        #pragma unroll
        for (int nt = 0; nt < 8; nt++) {
            float* c = acc[mt * 8 + nt];
            int col = n0 + wn * 64 + nt * 8 + 2 * t4;
            int r0  = m0 + wm * 32 + mt * 16 + g;
            #pragma unroll
            for (int hf = 0; hf < 2; hf++) {
                int row = r0 + hf * 8;
                __nv_bfloat16 eb = __hadd(__float2bfloat16(c[hf * 2 + 0]), bs[col]);
                __nv_bfloat16 ob = __hadd(__float2bfloat16(c[hf * 2 + 1]), bs[col + 1]);
                if (mode == 3) {
                    outF[(size_t)row * CC + col]     = __bfloat162float(eb);
                    outF[(size_t)row * CC + col + 1] = __bfloat162float(ob);
                } else {
                    int b = row >> 11, t = row & (TT - 1);
                    int h = col >> 6,  d = col & 63;
                    size_t oidx = ((size_t)(b * HH + h) * TT + t) * HD + d;
                    __nv_bfloat162 pr;
                    if (mode <= 1) {
                        int j = d >> 1;
                        float cth = g_cos[t * (HD/2) + j], sth = g_sin[t * (HD/2) + j];
                        float ef = __bfloat162float(eb), of = __bfloat162float(ob);
                        float re = __fsub_rn(__fmul_rn(ef, cth), __fmul_rn(of, sth));
                        float ro = __fadd_rn(__fmul_rn(ef, sth), __fmul_rn(of, cth));
                        pr.x = __float2bfloat16(re);
                        pr.y = __float2bfloat16(ro);
                    } else {
                        pr.x = eb; pr.y = ob;
                    }
                    __nv_bfloat16* outp = (mode == 0) ? g_q : (mode == 1) ? g_k : g_v;
                    *(__nv_bfloat162*)(outp + oidx) = pr;
                }
            }
        }
    }
}

// --------- fused attention (R15 structure + hoisted Q fragments) --------------
__global__ __launch_bounds__(256) void k_att()
{
    __shared__ __align__(16) unsigned char buf[36864];
    __shared__ float sMax[2][64];
    __shared__ float sMfin[64];
    __shared__ float sLfin[64];

    const int qt = gridDim.x - 1 - blockIdx.x;           // heavy tiles first
    const int bh = blockIdx.y;
    const int q0 = qt * 64;
    const __nv_bfloat16* __restrict__ Q = g_q + (size_t)bh * TT * HD;
    const __nv_bfloat16* __restrict__ K = g_k + (size_t)bh * TT * HD;
    const __nv_bfloat16* __restrict__ V = g_v + (size_t)bh * TT * HD;

    const int tid = threadIdx.x;
    const int wid = tid >> 5, lane = tid & 31;
    const int g = lane >> 2, t4 = lane & 3;
    const int wm = wid & 3, wn = wid >> 2;
    const int r0 = wm * 16 + g;
    const int lb = lane >> 3, lr = lane & 7;

    // ===================== phase A: S = bf16(QK^T)*0.125, max, l ==============
    {
        __nv_bfloat16* sQ = (__nv_bfloat16*)buf;
        #pragma unroll
        for (int rep = 0; rep < 2; rep++) {
            int i = tid + rep * 256;
            int row = i >> 3, cg = i & 7;
            *(uint4*)&sQ[row * 72 + cg * 8] = *(const uint4*)(Q + (size_t)(q0 + row) * HD + cg * 8);
        }
        #pragma unroll
        for (int rep = 0; rep < 2; rep++) {
            int i = tid + rep * 256;
            int row = i >> 3, cg = i & 7;
            uint32_t dst = (uint32_t)__cvta_generic_to_shared(buf + 9216 + (row * 72 + cg * 8) * 2);
            asm volatile("cp.async.cg.shared.global [%0], [%1], 16;\n"
                         :: "r"(dst), "l"(K + (size_t)row * HD + cg * 8));
        }
        asm volatile("cp.async.commit_group;\n");
        __syncthreads();                 // sQ visible -> hoist Q fragments once

        uint32_t qf[4][4];
        #pragma unroll
        for (int kq = 0; kq < 4; kq++) {
            int row = wm * 16 + (lb & 1) * 8 + lr;
            int col = kq * 16 + (lb >> 1) * 8;
            ldsm_x4(qf[kq], (uint32_t)__cvta_generic_to_shared(sQ + row * 72 + col));
        }

        const int qg0 = q0 + r0, qg1 = qg0 + 8;
        float rmax0 = -INFINITY, rmax1 = -INFINITY;

        for (int kt = 0; kt <= qt; kt++) {
            asm volatile("cp.async.wait_group 0;\n");
            __syncthreads();
            if (kt < qt) {
                unsigned char* dstb = buf + 9216 + ((kt + 1) & 1) * 9216;
                #pragma unroll
                for (int rep = 0; rep < 2; rep++) {
                    int i = tid + rep * 256;
                    int row = i >> 3, cg = i & 7;
                    uint32_t dst = (uint32_t)__cvta_generic_to_shared(dstb + (row * 72 + cg * 8) * 2);
                    asm volatile("cp.async.cg.shared.global [%0], [%1], 16;\n"
                                 :: "r"(dst), "l"(K + (size_t)((kt + 1) * 64 + row) * HD + cg * 8));
                }
                asm volatile("cp.async.commit_group;\n");
            }
            const __nv_bfloat16* sKb = (const __nv_bfloat16*)(buf + 9216 + (kt & 1) * 9216);
            float acc[4][4] = {};
            #pragma unroll
            for (int ks = 0; ks < 64; ks += 16) {
                uint32_t kf[4][2];
                #pragma unroll
                for (int p = 0; p < 2; p++) {
                    int row = wn * 32 + (2 * p + (lb >> 1)) * 8 + lr;
                    int col = ks + (lb & 1) * 8;
                    uint32_t q4[4];
                    ldsm_x4(q4, (uint32_t)__cvta_generic_to_shared(sKb + row * 72 + col));
                    kf[2 * p][0] = q4[0]; kf[2 * p][1] = q4[1];
                    kf[2 * p + 1][0] = q4[2]; kf[2 * p + 1][1] = q4[3];
                }
                #pragma unroll
                for (int nt = 0; nt < 4; nt++)
                    mma_bf16(acc[nt], qf[ks >> 4], kf[nt]);
            }
            #pragma unroll
            for (int nt = 0; nt < 4; nt++) {
                int cl = wn * 32 + nt * 8 + 2 * t4;
                int kc = kt * 64 + cl;
                {
                    float s0 = __fmul_rn(__bfloat162float(__float2bfloat16(acc[nt][0])), 0.125f);
                    float s1 = __fmul_rn(__bfloat162float(__float2bfloat16(acc[nt][1])), 0.125f);
                    if (kc     <= qg0) rmax0 = fmaxf(rmax0, s0);
                    if (kc + 1 <= qg0) rmax0 = fmaxf(rmax0, s1);
                    __nv_bfloat162 pr; pr.x = __float2bfloat16(s0); pr.y = __float2bfloat16(s1);
                    *(__nv_bfloat162*)(g_S + (size_t)(bh * TT + qg0) * TT + kc) = pr;
                }
                {
                    float s0 = __fmul_rn(__bfloat162float(__float2bfloat16(acc[nt][2])), 0.125f);
                    float s1 = __fmul_rn(__bfloat162float(__float2bfloat16(acc[nt][3])), 0.125f);
                    if (kc     <= qg1) rmax1 = fmaxf(rmax1, s0);
                    if (kc + 1 <= qg1) rmax1 = fmaxf(rmax1, s1);
                    __nv_bfloat162 pr; pr.x = __float2bfloat16(s0); pr.y = __float2bfloat16(s1);
                    *(__nv_bfloat162*)(g_S + (size_t)(bh * TT + qg1) * TT + kc) = pr;
                }
            }
        }
        rmax0 = fmaxf(rmax0, __shfl_xor_sync(0xffffffffu, rmax0, 1));
        rmax0 = fmaxf(rmax0, __shfl_xor_sync(0xffffffffu, rmax0, 2));
        rmax1 = fmaxf(rmax1, __shfl_xor_sync(0xffffffffu, rmax1, 1));
        rmax1 = fmaxf(rmax1, __shfl_xor_sync(0xffffffffu, rmax1, 2));
        if (t4 == 0) {
            sMax[wn][wm * 16 + g]     = rmax0;
            sMax[wn][wm * 16 + g + 8] = rmax1;
        }
        __syncthreads();
        if (tid < 64) sMfin[tid] = fmaxf(sMax[0][tid], sMax[1][tid]);
        __syncthreads();

        // V tile 0 prestage (sK buffers dead) — lands during the l-pass.
        #pragma unroll
        for (int rep = 0; rep < 2; rep++) {
            int i = tid + rep * 256;
            int row = i >> 3, cg = i & 7;
            uint32_t dst = (uint32_t)__cvta_generic_to_shared(buf + 18432 + (row * 72 + cg * 8) * 2);
            asm volatile("cp.async.cg.shared.global [%0], [%1], 16;\n"
                         :: "r"(dst), "l"(V + (size_t)row * HD + cg * 8));
        }
        asm volatile("cp.async.commit_group;\n");

        // l-pass: 4 independent add chains (2 packed f32x2 accumulators).
        {
            const int prow = tid >> 2;
            const int pcb  = (tid & 3) * 16;
            const int qgp  = q0 + prow;
            const float mrow = sMfin[prow];
            const __nv_bfloat16* __restrict__ Srow = g_S + (size_t)(bh * TT + qgp) * TT;
            uint64_t L0 = f32x2pk(0.f, 0.f), L1 = f32x2pk(0.f, 0.f);
            uint4 c0 = *(const uint4*)(Srow + pcb);
            uint4 c1 = *(const uint4*)(Srow + pcb + 8);
            for (int kt = 0; kt <= qt; kt++) {
                uint4 n0v, n1v;
                if (kt < qt) {
                    n0v = *(const uint4*)(Srow + (kt + 1) * 64 + pcb);
                    n1v = *(const uint4*)(Srow + (kt + 1) * 64 + pcb + 8);
                }
                __nv_bfloat16 hv[16];
                *(uint4*)&hv[0] = c0;
                *(uint4*)&hv[8] = c1;
                #pragma unroll
                for (int j = 0; j < 16; j += 4) {
                    int col = kt * 64 + pcb + j;
                    float e0, e1, e2, e3;
                    exp_rn2(__fsub_rn(__bfloat162float(hv[j]),     mrow),
                            __fsub_rn(__bfloat162float(hv[j + 1]), mrow), e0, e1);
                    exp_rn2(__fsub_rn(__bfloat162float(hv[j + 2]), mrow),
                            __fsub_rn(__bfloat162float(hv[j + 3]), mrow), e2, e3);
                    e0 = (col     <= qgp) ? e0 : 0.f;
                    e1 = (col + 1 <= qgp) ? e1 : 0.f;
                    e2 = (col + 2 <= qgp) ? e2 : 0.f;
                    e3 = (col + 3 <= qgp) ? e3 : 0.f;
                    L0 = add2(L0, f32x2pk(e0, e1));
                    L1 = add2(L1, f32x2pk(e2, e3));
                }
                c0 = n0v; c1 = n1v;
            }
            float a0, a1, b0, b1;
            f32x2upk(L0, a0, a1);
            f32x2upk(L1, b0, b1);
            float lp = __fadd_rn(__fadd_rn(__fadd_rn(a0, a1), b0), b1);
            lp = __fadd_rn(lp, __shfl_xor_sync(0xffffffffu, lp, 1));
            lp = __fadd_rn(lp, __shfl_xor_sync(0xffffffffu, lp, 2));
            if ((tid & 3) == 0) sLfin[qgp - q0] = lp;
        }
    }
    __syncthreads();   // sLfin ready; phase A smem (sQ/sK) dead from here

    // ===================== phase B: p = bf16(softmax), y = P@V^T ===============
    {
        const int prow = tid >> 2;
        const int pcb  = (tid & 3) * 16;
        const int qgp  = q0 + prow;
        const float mrow = sMfin[prow];
        const float lrow = sLfin[prow];
        const __nv_bfloat16* __restrict__ Srow = g_S + (size_t)(bh * TT + qgp) * TT;

        float acc[4][4] = {};
        const int l16 = lane & 15;

        uint4 s0 = *(const uint4*)(Srow + pcb);
        uint4 s1 = *(const uint4*)(Srow + pcb + 8);

        for (int kt = 0; kt <= qt; kt++) {
            const int bsel = kt & 1;
            __nv_bfloat16* sPb = (__nv_bfloat16*)(buf + bsel * 9216);
            const __nv_bfloat16* sVb = (const __nv_bfloat16*)(buf + 18432 + bsel * 9216);
            {
                __nv_bfloat16 hv[16];
                *(uint4*)&hv[0] = s0;
                *(uint4*)&hv[8] = s1;
                #pragma unroll
                for (int j = 0; j < 16; j += 2) {
                    int col = kt * 64 + pcb + j;
                    float e0, e1;
                    exp_rn2(__fsub_rn(__bfloat162float(hv[j]),     mrow),
                            __fsub_rn(__bfloat162float(hv[j + 1]), mrow), e0, e1);
                    __nv_bfloat162 pr;
                    pr.x = (col     <= qgp) ? __float2bfloat16(__fdiv_rn(e0, lrow))
                                            : __float2bfloat16(0.f);
                    pr.y = (col + 1 <= qgp) ? __float2bfloat16(__fdiv_rn(e1, lrow))
                                            : __float2bfloat16(0.f);
                    *(__nv_bfloat162*)&sPb[prow * 72 + pcb + j] = pr;
                }
            }
            asm volatile("cp.async.wait_group 0;\n");
            __syncthreads();
            if (kt < qt) {
                unsigned char* dstb = buf + 18432 + ((kt + 1) & 1) * 9216;
                #pragma unroll
                for (int rep = 0; rep < 2; rep++) {
                    int i = tid + rep * 256;
                    int row = i >> 3, cg = i & 7;
                    uint32_t dst = (uint32_t)__cvta_generic_to_shared(dstb + (row * 72 + cg * 8) * 2);
                    asm volatile("cp.async.cg.shared.global [%0], [%1], 16;\n"
                                 :: "r"(dst), "l"(V + (size_t)((kt + 1) * 64 + row) * HD + cg * 8));
                }
                asm volatile("cp.async.commit_group;\n");
                s0 = *(const uint4*)(Srow + (kt + 1) * 64 + pcb);
                s1 = *(const uint4*)(Srow + (kt + 1) * 64 + pcb + 8);
            }
            #pragma unroll
            for (int ks = 0; ks < 64; ks += 16) {
                uint32_t af[4];
                {
                    int row = wm * 16 + (lb & 1) * 8 + lr;
                    int col = ks + (lb >> 1) * 8;
                    ldsm_x4(af, (uint32_t)__cvta_generic_to_shared(sPb + row * 72 + col));
                }
                #pragma unroll
                for (int nt = 0; nt < 4; nt++) {
                    int n0c = wn * 32 + nt * 8;
                    uint32_t vaddr = (uint32_t)__cvta_generic_to_shared(
                        sVb + (size_t)(ks + l16) * 72 + n0c);
                    uint32_t b2[2];
                    asm volatile(
                        "ldmatrix.sync.aligned.m8n8.x2.trans.shared.b16 {%0,%1}, [%2];"
                        : "=r"(b2[0]), "=r"(b2[1]) : "r"(vaddr));
                    mma_bf16(acc[nt], af, b2);
                }
            }
        }

        const int b = bh >> 4, h = bh & 15;
        #pragma unroll
        for (int nt = 0; nt < 4; nt++) {
            int dcol = wn * 32 + nt * 8 + 2 * t4;
            #pragma unroll
            for (int hf = 0; hf < 2; hf++) {
                int trow = q0 + r0 + hf * 8;
                __nv_bfloat162 pr;
                pr.x = __float2bfloat16(acc[nt][hf * 2 + 0]);
                pr.y = __float2bfloat16(acc[nt][hf * 2 + 1]);
                *(__nv_bfloat162*)(g_y + (size_t)(b * TT + trow) * CC + h * HD + dcol) = pr;
            }
        }
    }
}

// ------------------------- launch ---------------------------------------------
extern "C" void kernel_launch(void* const* d_in, const int* in_sizes, int n_in,
                              void* d_out, int out_size)
{
    (void)in_sizes; (void)n_in; (void)out_size;
    const float* x  = (const float*)d_in[0];
    const float* Wq = (const float*)d_in[1];
    const float* bq = (const float*)d_in[2];
    const float* Wk = (const float*)d_in[3];
    const float* bk = (const float*)d_in[4];
    const float* Wv = (const float*)d_in[5];
    const float* bv = (const float*)d_in[6];
    const float* Wo = (const float*)d_in[7];
    const float* bo = (const float*)d_in[8];
    float* out = (float*)d_out;

    cudaFuncSetAttribute(k_gemm, cudaFuncAttributeMaxDynamicSharedMemorySize, GSMEM);

    k_conv_x  <<<(size_t)MM * CC / 1024, 256>>>(x);
    k_prepW   <<<dim3(32, 32, 4), dim3(32, 8)>>>(Wq, Wk, Wv, Wo, bq, bk, bv, bo);
    k_rope    <<<TT, 32>>>();
    k_gemm    <<<dim3(8, 64, 3), 256, GSMEM>>>(0, nullptr);   // q,k,v projections (+rope)
    k_att     <<<dim3(32, 64), 256>>>();                      // fused attention
    k_gemm    <<<dim3(8, 64, 1), 256, GSMEM>>>(3, out);       // output projection
}